// round 15
// baseline (speedup 1.0000x reference)
#include <cuda_runtime.h>
#include <stdint.h>
#include <math.h>

#define BB  4
#define TT  256
#define TS  512
#define HH  1024
#define VV  32100
#define NROW (BB*TT)
#define N4  8025            // float4 per row

#define HSLOTS 1024         // load factor 0.5 for <=512 unique ids
#define HMASK  (HSLOTS-1)

#define SEGF4   1024        // float4 per full segment (16 KB)
#define SEGB    16384
#define LASTF4  857         // seg 7: 8025 - 7*1024
#define LASTB   13712
#define NSEG    8
#define RING    3

// smem layout (bytes): ~57.7 KB -> 3 CTAs/SM (173 KB), 48 warps/SM
#define OFF_RING  0
#define OFF_HKEY  (RING*SEGB)                 // 49152
#define OFF_HVAL  (OFF_HKEY + HSLOTS*4)       // 53248
#define OFF_RED   (OFF_HVAL + HSLOTS*4)       // 57344
#define OFF_MBAR  (OFF_RED + 64*4)            // 57600
#define SMEM_TOT  (OFF_MBAR + RING*8 + 8)

__device__ float g_encproj[BB * TS];
__device__ float g_decproj[BB * TT];

__device__ __forceinline__ uint32_t smem_u32(const void* p) {
    uint32_t a;
    asm("{ .reg .u64 t; cvta.to.shared.u64 t, %1; cvt.u32.u64 %0, t; }"
        : "=r"(a) : "l"(p));
    return a;
}
__device__ __forceinline__ void mbar_init(uint32_t mbar, uint32_t cnt) {
    asm volatile("mbarrier.init.shared.b64 [%0], %1;" :: "r"(mbar), "r"(cnt) : "memory");
}
__device__ __forceinline__ void mbar_expect_tx(uint32_t mbar, uint32_t bytes) {
    asm volatile("mbarrier.arrive.expect_tx.shared.b64 _, [%0], %1;"
                 :: "r"(mbar), "r"(bytes) : "memory");
}
__device__ __forceinline__ void mbar_wait(uint32_t mbar, uint32_t phase) {
    asm volatile(
        "{\n\t.reg .pred P;\n\t"
        "W_%=:\n\t"
        "mbarrier.try_wait.parity.acquire.cta.shared::cta.b64 P, [%0], %1, 0x989680;\n\t"
        "@P bra D_%=;\n\t"
        "bra W_%=;\n\t"
        "D_%=:\n\t}"
        :: "r"(mbar), "r"(phase) : "memory");
}
__device__ __forceinline__ void tma_1d_g2s(uint32_t dst, const void* src,
                                           uint32_t bytes, uint32_t mbar) {
    asm volatile(
        "cp.async.bulk.shared::cta.global.mbarrier::complete_tx::bytes [%0], [%1], %2, [%3];"
        :: "r"(dst), "l"(src), "r"(bytes), "r"(mbar) : "memory");
}

// ---------------------------------------------------------------------------
// Kernel 1: one warp per dot; replaces the einsum via
//   context . W_top == sum_s attn[s] * (enc[s] . W_top)
// Ends with griddepcontrol.launch_dependents for PDL overlap.
// ---------------------------------------------------------------------------
__global__ void proj_kernel(const float* __restrict__ dec,
                            const float* __restrict__ enc,
                            const float* __restrict__ Wg,
                            const float* __restrict__ bg)
{
    const int gw   = (blockIdx.x * blockDim.x + threadIdx.x) >> 5;
    const int lane = threadIdx.x & 31;
    const int nEnc = BB * TS;
    const int nDec = BB * TT;

    if (gw < nEnc) {
        const float4* row = (const float4*)(enc + (size_t)gw * HH);
        const float4* w   = (const float4*)(Wg);
        float s = 0.f;
        #pragma unroll
        for (int i = 0; i < HH / 128; ++i) {
            float4 a = row[lane + i * 32];
            float4 b = w[lane + i * 32];
            s += a.x * b.x + a.y * b.y + a.z * b.z + a.w * b.w;
        }
        #pragma unroll
        for (int o = 16; o > 0; o >>= 1) s += __shfl_xor_sync(0xffffffffu, s, o);
        if (lane == 0) g_encproj[gw] = s;
    } else if (gw < nEnc + nDec) {
        const int r = gw - nEnc;
        const float4* row = (const float4*)(dec + (size_t)r * HH);
        const float4* w   = (const float4*)(Wg + HH);
        float s = 0.f;
        #pragma unroll
        for (int i = 0; i < HH / 128; ++i) {
            float4 a = row[lane + i * 32];
            float4 b = w[lane + i * 32];
            s += a.x * b.x + a.y * b.y + a.z * b.z + a.w * b.w;
        }
        #pragma unroll
        for (int o = 16; o > 0; o >>= 1) s += __shfl_xor_sync(0xffffffffu, s, o);
        if (lane == 0) g_decproj[r] = s + bg[0];
    }
    __threadfence();
    asm volatile("griddepcontrol.launch_dependents;" ::: "memory");
}

__device__ __forceinline__ float4 xform(float4 x, float c, float pinvS, bool fastp) {
    float4 r;
    if (fastp) {
        r.x = x.x + c; r.y = x.y + c; r.z = x.z + c; r.w = x.w + c;
    } else {
        r.x = __logf(fmaf(pinvS, __expf(x.x), 1e-12f));
        r.y = __logf(fmaf(pinvS, __expf(x.y), 1e-12f));
        r.z = __logf(fmaf(pinvS, __expf(x.z), 1e-12f));
        r.w = __logf(fmaf(pinvS, __expf(x.w), 1e-12f));
    }
    return r;
}

// ---------------------------------------------------------------------------
// Kernel 2: one CTA (512 thr) per row, 3 CTAs/SM (L2-correct operating point).
// Pass 1: 3-slot TMA ring streams the row into smem for sum-exp/min (DRAM read).
// Pass 2: plain unrolled LDG re-read (L2-hot) + xform + store — no ring, no
// mbar waits, no syncs; pipelines freely against the other 2 CTAs on the SM.
// ---------------------------------------------------------------------------
__global__ __launch_bounds__(512, 3)
void pgen_main(const float* __restrict__ attn,
               const float* __restrict__ logits,
               const int*   __restrict__ sids,
               float*       __restrict__ out)
{
    extern __shared__ __align__(128) char smem[];
    float4* ring = (float4*)(smem + OFF_RING);
    int*    hkey = (int*)  (smem + OFF_HKEY);
    float*  hval = (float*)(smem + OFF_HVAL);
    float*  red  = (float*)(smem + OFF_RED);
    const uint32_t mbar0   = smem_u32(smem + OFF_MBAR);
    const uint32_t ringdst = smem_u32(smem + OFF_RING);

    const int t    = threadIdx.x;
    const int warp = t >> 5;          // 0..15
    const int lane = t & 31;
    const int row  = blockIdx.x;
    const int b    = row / TT;

    // init hash (2 slots/thread) + ring mbarriers
    hkey[t] = -1;        hval[t] = 0.f;
    hkey[t + 512] = -1;  hval[t + 512] = 0.f;
    if (t == 0) {
        #pragma unroll
        for (int j = 0; j < RING; ++j) mbar_init(mbar0 + j * 8, 1);
    }
    __syncthreads();

    // kick segments 0,1,2 (all full-size)
    const float*  lrow  = logits + (size_t)row * VV;
    const float4* lrow4 = (const float4*)lrow;
    if (t == 0) {
        #pragma unroll
        for (int j = 0; j < RING; ++j) {
            mbar_expect_tx(mbar0 + j * 8, SEGB);
            tma_1d_g2s(ringdst + j * SEGB, lrow4 + j * SEGF4, SEGB, mbar0 + j * 8);
        }
    }

    // scatter (proj-independent): every thread owns one source position
    const float a0  = attn[(size_t)row * TS + t];
    const int   id0 = sids[b * TS + t];
    {
        int slot = (int)(((unsigned)id0 * 2654435761u) >> 17) & HMASK;
        for (;;) {
            int prev = atomicCAS(&hkey[slot], -1, id0);
            if (prev == -1 || prev == id0) { atomicAdd(&hval[slot], a0); break; }
            slot = (slot + 1) & HMASK;
        }
    }

    // ---- pass 1: stream segments 0..7 through the ring, sum exp + min ----
    float se = 0.f, xmn = 1e30f;
    #pragma unroll
    for (int s = 0; s < NSEG; ++s) {
        const int slot = s % RING;
        const int ph   = (s / RING) & 1;
        mbar_wait(mbar0 + slot * 8, ph);
        const float4* seg = ring + slot * SEGF4;
        const int cnt = (s < 7) ? SEGF4 : LASTF4;
        if (t < cnt) {
            const float4 x = seg[t];
            se += __expf(x.x) + __expf(x.y) + __expf(x.z) + __expf(x.w);
            xmn = fminf(xmn, fminf(fminf(x.x, x.y), fminf(x.z, x.w)));
        }
        if (t + 512 < cnt) {
            const float4 x = seg[t + 512];
            se += __expf(x.x) + __expf(x.y) + __expf(x.z) + __expf(x.w);
            xmn = fminf(xmn, fminf(fminf(x.x, x.y), fminf(x.z, x.w)));
        }
        const int ls = s + RING;               // next segment into this slot
        if (ls < NSEG) {
            __syncthreads();                   // slot fully consumed
            if (t == 0) {
                const uint32_t bytes = (ls < 7) ? SEGB : LASTB;
                mbar_expect_tx(mbar0 + slot * 8, bytes);
                tma_1d_g2s(ringdst + slot * SEGB, lrow4 + ls * SEGF4,
                           bytes, mbar0 + slot * 8);
            }
        }
    }

    // ---- PDL join: proj results needed from here on ----
    asm volatile("griddepcontrol.wait;" ::: "memory");
    float pg = a0 * g_encproj[b * TS + t];

    // ---- block reduction of (pg, se, xmn) over 16 warps ----
    #pragma unroll
    for (int o = 16; o > 0; o >>= 1) {
        pg += __shfl_xor_sync(0xffffffffu, pg, o);
        se += __shfl_xor_sync(0xffffffffu, se, o);
        xmn = fminf(xmn, __shfl_xor_sync(0xffffffffu, xmn, o));
    }
    if (lane == 0) { red[warp] = pg; red[16 + warp] = se; red[32 + warp] = xmn; }
    __syncthreads();
    if (warp == 0 && lane < 16) {
        float a2 = red[lane];
        float s2 = red[16 + lane];
        float m2 = red[32 + lane];
        #pragma unroll
        for (int o = 8; o > 0; o >>= 1) {
            a2 += __shfl_xor_sync(0xffffu, a2, o);
            s2 += __shfl_xor_sync(0xffffu, s2, o);
            m2  = fminf(m2, __shfl_xor_sync(0xffffu, m2, o));
        }
        if (lane == 0) { red[0] = a2; red[16] = s2; red[32] = m2; }
    }
    __syncthreads();

    const float z     = red[0] + g_decproj[row];
    const float p     = 1.f / (1.f + __expf(-z));
    const float q     = 1.f - p;
    const float pinvS = p / red[16];
    const float c     = __logf(pinvS);
    const bool  fastp = (pinvS * __expf(red[32])) >= 1e-9f;

    // ---- pass 2: direct LDG re-read (L2-hot), xform + store. No syncs. ----
    float4* orow4 = (float4*)(out + (size_t)row * VV);
    if (fastp) {
        #pragma unroll 4
        for (int i = t; i < N4; i += 512) {
            const float4 x = lrow4[i];
            float4 r;
            r.x = x.x + c; r.y = x.y + c; r.z = x.z + c; r.w = x.w + c;
            orow4[i] = r;
        }
    } else {
        #pragma unroll 4
        for (int i = t; i < N4; i += 512) {
            orow4[i] = xform(lrow4[i], c, pinvS, false);
        }
    }

    // order all pass-2 stores before fixup overwrites
    __syncthreads();

    // ---- fixup: 2 hash slots/thread; overwrite copy positions ----
    float* osc = out + (size_t)row * VV;
    #pragma unroll
    for (int i = 0; i < 2; ++i) {
        const int s   = t + i * 512;
        const int vid = hkey[s];
        if (vid >= 0) {
            const float x = lrow[vid];   // L2-hot
            osc[vid] = __logf(fmaf(pinvS, __expf(x), fmaf(q, hval[s], 1e-12f)));
        }
    }
}

extern "C" void kernel_launch(void* const* d_in, const int* in_sizes, int n_in,
                              void* d_out, int out_size)
{
    const float* dec    = (const float*)d_in[0];
    const float* attn   = (const float*)d_in[1];
    const float* enc    = (const float*)d_in[2];
    const float* logits = (const float*)d_in[3];
    const float* Wg     = (const float*)d_in[4];
    const float* bg     = (const float*)d_in[5];
    const int*   sids   = (const int*)  d_in[6];
    float*       out    = (float*)d_out;

    cudaFuncSetAttribute(pgen_main,
                         cudaFuncAttributeMaxDynamicSharedMemorySize, SMEM_TOT);

    proj_kernel<<<(BB * TS + BB * TT) / 8, 256>>>(dec, enc, Wg, bg);

    // PDL launch: pgen_main may start under proj; gates itself with
    // griddepcontrol.wait before first use of proj outputs.
    cudaLaunchConfig_t cfg = {};
    cfg.gridDim          = dim3(NROW, 1, 1);
    cfg.blockDim         = dim3(512, 1, 1);
    cfg.dynamicSmemBytes = SMEM_TOT;
    cfg.stream           = 0;
    cudaLaunchAttribute at[1];
    at[0].id = cudaLaunchAttributeProgrammaticStreamSerialization;
    at[0].val.programmaticStreamSerializationAllowed = 1;
    cfg.attrs    = at;
    cfg.numAttrs = 1;
    cudaLaunchKernelEx(&cfg, pgen_main, attn, logits, sids, out);
}

// round 16
// speedup vs baseline: 1.1718x; 1.1718x over previous
#include <cuda_runtime.h>
#include <stdint.h>
#include <math.h>

#define BB  4
#define TT  256
#define TS  512
#define HH  1024
#define VV  32100
#define NROW (BB*TT)
#define N4  8025            // float4 per row

#define HSLOTS 2048
#define HMASK  (HSLOTS-1)

#define SEGF4   1024        // float4 per full segment (16 KB)
#define SEGB    16384
#define LASTF4  857
#define LASTB   13712
#define NSEG    8           // per pass; 16 logical segments total
#define RING    3

// smem layout (bytes): ~65.9 KB -> 3 CTAs/SM
#define OFF_RING  0
#define OFF_HKEY  (RING*SEGB)                 // 49152
#define OFF_HVAL  (OFF_HKEY + HSLOTS*4)       // 57344
#define OFF_RED   (OFF_HVAL + HSLOTS*4)       // 65536
#define OFF_MBAR  (OFF_RED + 64*4)            // 65792: full[3]@0,8,16 empty[3]@24,32,40
#define SMEM_TOT  (OFF_MBAR + 48 + 16)

__device__ float g_encproj[BB * TS];
__device__ float g_decproj[BB * TT];

__device__ __forceinline__ uint32_t smem_u32(const void* p) {
    uint32_t a;
    asm("{ .reg .u64 t; cvta.to.shared.u64 t, %1; cvt.u32.u64 %0, t; }"
        : "=r"(a) : "l"(p));
    return a;
}
__device__ __forceinline__ void mbar_init(uint32_t mbar, uint32_t cnt) {
    asm volatile("mbarrier.init.shared.b64 [%0], %1;" :: "r"(mbar), "r"(cnt) : "memory");
}
__device__ __forceinline__ void mbar_expect_tx(uint32_t mbar, uint32_t bytes) {
    asm volatile("mbarrier.arrive.expect_tx.shared.b64 _, [%0], %1;"
                 :: "r"(mbar), "r"(bytes) : "memory");
}
__device__ __forceinline__ void mbar_arrive(uint32_t mbar) {
    asm volatile("mbarrier.arrive.shared.b64 _, [%0];" :: "r"(mbar) : "memory");
}
__device__ __forceinline__ void mbar_wait(uint32_t mbar, uint32_t phase) {
    asm volatile(
        "{\n\t.reg .pred P;\n\t"
        "W_%=:\n\t"
        "mbarrier.try_wait.parity.acquire.cta.shared::cta.b64 P, [%0], %1, 0x989680;\n\t"
        "@P bra D_%=;\n\t"
        "bra W_%=;\n\t"
        "D_%=:\n\t}"
        :: "r"(mbar), "r"(phase) : "memory");
}
__device__ __forceinline__ void tma_1d_g2s(uint32_t dst, const void* src,
                                           uint32_t bytes, uint32_t mbar) {
    asm volatile(
        "cp.async.bulk.shared::cta.global.mbarrier::complete_tx::bytes [%0], [%1], %2, [%3];"
        :: "r"(dst), "l"(src), "r"(bytes), "r"(mbar) : "memory");
}

// ---------------------------------------------------------------------------
// Kernel 1: one warp per dot; replaces the einsum via
//   context . W_top == sum_s attn[s] * (enc[s] . W_top)
// ---------------------------------------------------------------------------
__global__ void proj_kernel(const float* __restrict__ dec,
                            const float* __restrict__ enc,
                            const float* __restrict__ Wg,
                            const float* __restrict__ bg)
{
    const int gw   = (blockIdx.x * blockDim.x + threadIdx.x) >> 5;
    const int lane = threadIdx.x & 31;
    const int nEnc = BB * TS;
    const int nDec = BB * TT;

    if (gw < nEnc) {
        const float4* row = (const float4*)(enc + (size_t)gw * HH);
        const float4* w   = (const float4*)(Wg);
        float s = 0.f;
        #pragma unroll
        for (int i = 0; i < HH / 128; ++i) {
            float4 a = row[lane + i * 32];
            float4 b = w[lane + i * 32];
            s += a.x * b.x + a.y * b.y + a.z * b.z + a.w * b.w;
        }
        #pragma unroll
        for (int o = 16; o > 0; o >>= 1) s += __shfl_xor_sync(0xffffffffu, s, o);
        if (lane == 0) g_encproj[gw] = s;
    } else if (gw < nEnc + nDec) {
        const int r = gw - nEnc;
        const float4* row = (const float4*)(dec + (size_t)r * HH);
        const float4* w   = (const float4*)(Wg + HH);
        float s = 0.f;
        #pragma unroll
        for (int i = 0; i < HH / 128; ++i) {
            float4 a = row[lane + i * 32];
            float4 b = w[lane + i * 32];
            s += a.x * b.x + a.y * b.y + a.z * b.z + a.w * b.w;
        }
        #pragma unroll
        for (int o = 16; o > 0; o >>= 1) s += __shfl_xor_sync(0xffffffffu, s, o);
        if (lane == 0) g_decproj[r] = s + bg[0];
    }
}

__device__ __forceinline__ float4 xform(float4 x, float c, float pinvS, bool fastp) {
    float4 r;
    if (fastp) {
        r.x = x.x + c; r.y = x.y + c; r.z = x.z + c; r.w = x.w + c;
    } else {
        r.x = __logf(fmaf(pinvS, __expf(x.x), 1e-12f));
        r.y = __logf(fmaf(pinvS, __expf(x.y), 1e-12f));
        r.z = __logf(fmaf(pinvS, __expf(x.z), 1e-12f));
        r.w = __logf(fmaf(pinvS, __expf(x.w), 1e-12f));
    }
    return r;
}

// ---------------------------------------------------------------------------
// Kernel 2: one CTA (512 thr) per row, 3 CTAs/SM. Row streams twice through a
// 3-slot TMA ring; 16 logical segments (slot=s%3, phase=(s/3)&1). Producer/
// consumer mbarriers: consumers free-run (wait full -> consume -> arrive
// empty); only t0 waits the empty-drain before re-kicking a slot's TMA.
// Block syncs per row: 4 (vs 16 in the round-12 version).
// ---------------------------------------------------------------------------
__global__ __launch_bounds__(512, 3)
void pgen_main(const float* __restrict__ attn,
               const float* __restrict__ logits,
               const int*   __restrict__ sids,
               float*       __restrict__ out)
{
    extern __shared__ __align__(128) char smem[];
    float4* ring = (float4*)(smem + OFF_RING);
    int*    hkey = (int*)  (smem + OFF_HKEY);
    float*  hval = (float*)(smem + OFF_HVAL);
    float*  red  = (float*)(smem + OFF_RED);
    const uint32_t full0   = smem_u32(smem + OFF_MBAR);
    const uint32_t empty0  = smem_u32(smem + OFF_MBAR + 24);
    const uint32_t ringdst = smem_u32(smem + OFF_RING);

    const int t    = threadIdx.x;
    const int warp = t >> 5;          // 0..15
    const int lane = t & 31;
    const int row  = blockIdx.x;
    const int b    = row / TT;

    // init hash (4 slots/thread) + mbarriers
    #pragma unroll
    for (int i = 0; i < 4; ++i) { hkey[t + i * 512] = -1; hval[t + i * 512] = 0.f; }
    if (t == 0) {
        #pragma unroll
        for (int j = 0; j < RING; ++j) {
            mbar_init(full0  + j * 8, 1);
            mbar_init(empty0 + j * 8, 512);
        }
    }
    __syncthreads();

    // kick segments 0,1,2 (all full-size; no empty wait on first use)
    const float*  lrow  = logits + (size_t)row * VV;
    const float4* lrow4 = (const float4*)lrow;
    if (t == 0) {
        #pragma unroll
        for (int j = 0; j < RING; ++j) {
            mbar_expect_tx(full0 + j * 8, SEGB);
            tma_1d_g2s(ringdst + j * SEGB, lrow4 + j * SEGF4, SEGB, full0 + j * 8);
        }
    }

    // scatter (every thread owns one source position)
    const float a0  = attn[(size_t)row * TS + t];
    const int   id0 = sids[b * TS + t];
    {
        int slot = (int)(((unsigned)id0 * 2654435761u) >> 17) & HMASK;
        for (;;) {
            int prev = atomicCAS(&hkey[slot], -1, id0);
            if (prev == -1 || prev == id0) { atomicAdd(&hval[slot], a0); break; }
            slot = (slot + 1) & HMASK;
        }
    }
    float pg = a0 * g_encproj[b * TS + t];

    // ---- pass 1: segments 0..7, sum exp + min; consumers free-run ----
    float se = 0.f, xmn = 1e30f;
    #pragma unroll
    for (int s = 0; s < NSEG; ++s) {
        const int slot = s % RING;
        const int ph   = (s / RING) & 1;
        mbar_wait(full0 + slot * 8, ph);
        const float4* seg = ring + slot * SEGF4;
        const int cnt = (s < 7) ? SEGF4 : LASTF4;
        if (t < cnt) {
            const float4 x = seg[t];
            se += __expf(x.x) + __expf(x.y) + __expf(x.z) + __expf(x.w);
            xmn = fminf(xmn, fminf(fminf(x.x, x.y), fminf(x.z, x.w)));
        }
        if (t + 512 < cnt) {
            const float4 x = seg[t + 512];
            se += __expf(x.x) + __expf(x.y) + __expf(x.z) + __expf(x.w);
            xmn = fminf(xmn, fminf(fminf(x.x, x.y), fminf(x.z, x.w)));
        }
        mbar_arrive(empty0 + slot * 8);
        // producer: once this slot is drained by all 512 threads, re-kick it
        if (t == 0 && s + RING < 2 * NSEG) {
            mbar_wait(empty0 + slot * 8, ph);    // empty phase parity == (s/3)&1
            const int off = (s + RING) & 7;      // logical seg 8..15 -> offsets 0..7
            const uint32_t bytes = (off < 7) ? SEGB : LASTB;
            mbar_expect_tx(full0 + slot * 8, bytes);
            tma_1d_g2s(ringdst + slot * SEGB, lrow4 + off * SEGF4,
                       bytes, full0 + slot * 8);
        }
    }

    // ---- block reduction of (pg, se, xmn) over 16 warps ----
    #pragma unroll
    for (int o = 16; o > 0; o >>= 1) {
        pg += __shfl_xor_sync(0xffffffffu, pg, o);
        se += __shfl_xor_sync(0xffffffffu, se, o);
        xmn = fminf(xmn, __shfl_xor_sync(0xffffffffu, xmn, o));
    }
    if (lane == 0) { red[warp] = pg; red[16 + warp] = se; red[32 + warp] = xmn; }
    __syncthreads();
    if (warp == 0 && lane < 16) {
        float a2 = red[lane];
        float s2 = red[16 + lane];
        float m2 = red[32 + lane];
        #pragma unroll
        for (int o = 8; o > 0; o >>= 1) {
            a2 += __shfl_xor_sync(0xffffu, a2, o);
            s2 += __shfl_xor_sync(0xffffu, s2, o);
            m2  = fminf(m2, __shfl_xor_sync(0xffffu, m2, o));
        }
        if (lane == 0) { red[0] = a2; red[16] = s2; red[32] = m2; }
    }
    __syncthreads();

    const float z     = red[0] + g_decproj[row];
    const float p     = 1.f / (1.f + __expf(-z));
    const float q     = 1.f - p;
    const float pinvS = p / red[16];
    const float c     = __logf(pinvS);
    const bool  fastp = (pinvS * __expf(red[32])) >= 1e-9f;

    // ---- pass 2: segments 8..15 (L2-hot re-read), xform + store ----
    float4* orow4 = (float4*)(out + (size_t)row * VV);
    #pragma unroll
    for (int s = NSEG; s < 2 * NSEG; ++s) {
        const int slot = s % RING;
        const int ph   = (s / RING) & 1;
        mbar_wait(full0 + slot * 8, ph);
        const float4* seg  = ring + slot * SEGF4;
        const int     off  = s - NSEG;
        const int     base = off * SEGF4;
        const int     cnt  = (off < 7) ? SEGF4 : LASTF4;
        if (t < cnt)       orow4[base + t]       = xform(seg[t],       c, pinvS, fastp);
        if (t + 512 < cnt) orow4[base + t + 512] = xform(seg[t + 512], c, pinvS, fastp);
        mbar_arrive(empty0 + slot * 8);
        if (t == 0 && s + RING < 2 * NSEG) {
            mbar_wait(empty0 + slot * 8, ph);
            const int off2 = (s + RING) & 7;
            const uint32_t bytes = (off2 < 7) ? SEGB : LASTB;
            mbar_expect_tx(full0 + slot * 8, bytes);
            tma_1d_g2s(ringdst + slot * SEGB, lrow4 + off2 * SEGF4,
                       bytes, full0 + slot * 8);
        }
    }

    // order all pass-2 stores before fixup overwrites
    __syncthreads();

    // ---- fixup: 4 hash slots/thread; overwrite copy positions ----
    float* osc = out + (size_t)row * VV;
    #pragma unroll
    for (int i = 0; i < 4; ++i) {
        const int s   = t + i * 512;
        const int vid = hkey[s];
        if (vid >= 0) {
            const float x = lrow[vid];   // L2-hot
            osc[vid] = __logf(fmaf(pinvS, __expf(x), fmaf(q, hval[s], 1e-12f)));
        }
    }
}

extern "C" void kernel_launch(void* const* d_in, const int* in_sizes, int n_in,
                              void* d_out, int out_size)
{
    const float* dec    = (const float*)d_in[0];
    const float* attn   = (const float*)d_in[1];
    const float* enc    = (const float*)d_in[2];
    const float* logits = (const float*)d_in[3];
    const float* Wg     = (const float*)d_in[4];
    const float* bg     = (const float*)d_in[5];
    const int*   sids   = (const int*)  d_in[6];
    float*       out    = (float*)d_out;

    cudaFuncSetAttribute(pgen_main,
                         cudaFuncAttributeMaxDynamicSharedMemorySize, SMEM_TOT);

    proj_kernel<<<(BB * TS + BB * TT) / 8, 256>>>(dec, enc, Wg, bg);
    pgen_main<<<NROW, 512, SMEM_TOT>>>(attn, logits, sids, out);
}